// round 9
// baseline (speedup 1.0000x reference)
#include <cuda_runtime.h>
#include <cuda_bf16.h>
#include <cstdint>

// Problem constants
#define B_SZ 4
#define S_LEN 2048
#define EMB 1024
#define NH 16
#define DH 64
#define M_ROWS (B_SZ * S_LEN)   // 8192

// ---------------------------------------------------------------------------
// Scratch (static device globals; no runtime allocation)
// ---------------------------------------------------------------------------
__device__ float g_Q[(size_t)M_ROWS * EMB];
__device__ float g_K[(size_t)M_ROWS * EMB];
__device__ float g_V[(size_t)M_ROWS * EMB];
__device__ float g_O[(size_t)M_ROWS * EMB];

// ---------------------------------------------------------------------------
// tf32 helpers
// ---------------------------------------------------------------------------
__device__ __forceinline__ uint32_t f2tf(float x) {
    uint32_t u;
    asm("cvt.rna.tf32.f32 %0, %1;" : "=r"(u) : "f"(x));
    return u;
}

__device__ __forceinline__ void mma_tf32(float* c, const uint32_t* a, const uint32_t* b) {
    asm volatile(
        "mma.sync.aligned.m16n8k8.row.col.f32.tf32.tf32.f32 "
        "{%0,%1,%2,%3}, {%4,%5,%6,%7}, {%8,%9}, {%0,%1,%2,%3};\n"
        : "+f"(c[0]), "+f"(c[1]), "+f"(c[2]), "+f"(c[3])
        : "r"(a[0]), "r"(a[1]), "r"(a[2]), "r"(a[3]), "r"(b[0]), "r"(b[1]));
}

// ---------------------------------------------------------------------------
// tf32 GEMM: C[M,N] = A[M,K] @ B[N,K]^T  (both K-contiguous -> row.col mma)
// 128x128 block, BK=32, 8 warps (2m x 4n), warp tile 64x32.
// Double-buffered smem, ONE __syncthreads per 32-K stage.
// ---------------------------------------------------------------------------
#define GST 36   // 36 mod 32 = 4 -> conflict-free fragment reads
#define GNS (EMB / 32)   // 32 stages

__global__ __launch_bounds__(256) void tfgemm_nt(const float* __restrict__ A,
                                                 const float* __restrict__ B,
                                                 float* __restrict__ C,
                                                 int M, int N, int K) {
    extern __shared__ float gsm[];
    // two stages: [stage][A/B][128][GST]
    float* As[2] = {gsm,                gsm + 2 * 128 * GST};
    float* Bs[2] = {gsm + 128 * GST,    gsm + 3 * 128 * GST};

    const int tid  = threadIdx.x;
    const int lane = tid & 31;
    const int wid  = tid >> 5;
    const int wm   = wid >> 2;      // 0..1 -> 64-row slice
    const int wn   = wid & 3;       // 0..3 -> 32-col slice
    const int g    = lane >> 2;
    const int t    = lane & 3;

    const int bm = blockIdx.y * 128;
    const int bn = blockIdx.x * 128;

    float c[4][4][4];
#pragma unroll
    for (int mt = 0; mt < 4; mt++)
#pragma unroll
        for (int nt = 0; nt < 4; nt++)
#pragma unroll
            for (int i = 0; i < 4; i++) c[mt][nt][i] = 0.f;

    const float* Ap = A + (size_t)bm * K;
    const float* Bp = B + (size_t)bn * K;

    // loader coords: 128 rows x 8 float4 = 1024 per tensor; 4 per thread
    int lr[4], lc[4];
#pragma unroll
    for (int i = 0; i < 4; i++) {
        int idx = tid + i * 256;
        lr[i] = idx >> 3;
        lc[i] = (idx & 7) << 2;
    }

    float4 av[4], bv[4];
#pragma unroll
    for (int i = 0; i < 4; i++) {
        av[i] = *reinterpret_cast<const float4*>(Ap + (size_t)lr[i] * K + lc[i]);
        bv[i] = *reinterpret_cast<const float4*>(Bp + (size_t)lr[i] * K + lc[i]);
    }

    for (int s = 0; s < GNS; s++) {
        const int buf = s & 1;
        float* Asb = As[buf];
        float* Bsb = Bs[buf];

        // store current stage (regs -> smem, tf32-rounded)
#pragma unroll
        for (int i = 0; i < 4; i++) {
            float* da = &Asb[lr[i] * GST + lc[i]];
            da[0] = __uint_as_float(f2tf(av[i].x));
            da[1] = __uint_as_float(f2tf(av[i].y));
            da[2] = __uint_as_float(f2tf(av[i].z));
            da[3] = __uint_as_float(f2tf(av[i].w));
            float* db = &Bsb[lr[i] * GST + lc[i]];
            db[0] = __uint_as_float(f2tf(bv[i].x));
            db[1] = __uint_as_float(f2tf(bv[i].y));
            db[2] = __uint_as_float(f2tf(bv[i].z));
            db[3] = __uint_as_float(f2tf(bv[i].w));
        }

        // prefetch next stage to regs (lands during compute below)
        if (s + 1 < GNS) {
            const int k0 = (s + 1) * 32;
#pragma unroll
            for (int i = 0; i < 4; i++) {
                av[i] = *reinterpret_cast<const float4*>(Ap + (size_t)lr[i] * K + k0 + lc[i]);
                bv[i] = *reinterpret_cast<const float4*>(Bp + (size_t)lr[i] * K + k0 + lc[i]);
            }
        }

        __syncthreads();   // the ONLY barrier per stage

        // compute: 4 k-steps x (4 mt x 4 nt) MMAs
#pragma unroll
        for (int ks = 0; ks < 4; ks++) {
            const int kk = ks * 8;
            uint32_t a[4][4];
#pragma unroll
            for (int mt = 0; mt < 4; mt++) {
                const int r = wm * 64 + mt * 16;
                a[mt][0] = __float_as_uint(Asb[(r + g) * GST + kk + t]);
                a[mt][1] = __float_as_uint(Asb[(r + g + 8) * GST + kk + t]);
                a[mt][2] = __float_as_uint(Asb[(r + g) * GST + kk + t + 4]);
                a[mt][3] = __float_as_uint(Asb[(r + g + 8) * GST + kk + t + 4]);
            }
            uint32_t b[4][2];
#pragma unroll
            for (int nt = 0; nt < 4; nt++) {
                const int n = wn * 32 + nt * 8;
                b[nt][0] = __float_as_uint(Bsb[(n + g) * GST + kk + t]);
                b[nt][1] = __float_as_uint(Bsb[(n + g) * GST + kk + t + 4]);
            }
#pragma unroll
            for (int mt = 0; mt < 4; mt++)
#pragma unroll
                for (int nt = 0; nt < 4; nt++)
                    mma_tf32(c[mt][nt], a[mt], b[nt]);
        }
    }

#pragma unroll
    for (int mt = 0; mt < 4; mt++) {
#pragma unroll
        for (int nt = 0; nt < 4; nt++) {
            const int r  = bm + wm * 64 + mt * 16 + g;
            const int cn = bn + wn * 32 + nt * 8 + 2 * t;
            *reinterpret_cast<float2*>(C + (size_t)r * N + cn) =
                make_float2(c[mt][nt][0], c[mt][nt][1]);
            *reinterpret_cast<float2*>(C + (size_t)(r + 8) * N + cn) =
                make_float2(c[mt][nt][2], c[mt][nt][3]);
        }
    }
}

// ---------------------------------------------------------------------------
// Fused causal flash attention, tf32 mma.sync.
// BQ=128 q-rows per CTA, 8 warps; warp w owns rows [16w,16w+16) x ALL 64 kv
// cols -> softmax is warp-local (no cross-warp smem/barriers). Row state in
// registers. P roundtrip through warp-private smem, __syncwarp only.
// ---------------------------------------------------------------------------
#define AST 68   // 68 mod 32 = 4
#define VST 72   // 72 mod 32 = 8

__global__ __launch_bounds__(256) void attn_tc(const float* __restrict__ Q,
                                               const float* __restrict__ K,
                                               const float* __restrict__ V,
                                               float* __restrict__ O) {
    extern __shared__ float sm[];
    float* Qs = sm;                  // [128][AST]
    float* Ks = Qs + 128 * AST;      // [64][AST]
    float* Ps = Ks + 64 * AST;       // [128][AST]
    float* Vs = Ps + 128 * AST;      // [64][VST]

    const int tid  = threadIdx.x;
    const int lane = tid & 31;
    const int wid  = tid >> 5;
    const int g    = lane >> 2;
    const int t    = lane & 3;
    const int m0   = wid * 16;       // warp's row slice

    const int iq = (gridDim.x - 1) - blockIdx.x;   // heaviest CTAs first
    const int h  = blockIdx.y;
    const int b  = blockIdx.z;
    const size_t base = ((size_t)b * S_LEN) * EMB + (size_t)h * DH;

    // kv loader coords: 64 rows x 16 float4 = 1024; 4 per thread
    int krow[4], kc4[4];
#pragma unroll
    for (int it = 0; it < 4; it++) {
        int idx = tid + it * 256;
        krow[it] = idx >> 4;
        kc4[it]  = (idx & 15) << 2;
    }

    // Load Q tile: 128 rows x 16 float4 = 2048; 8 per thread (scaled, tf32)
    {
        const float* gq = Q + base + (size_t)iq * 128 * EMB;
#pragma unroll
        for (int it = 0; it < 8; it++) {
            int idx = tid + it * 256;
            int row = idx >> 4;
            int c4  = (idx & 15) << 2;
            float4 qv = *reinterpret_cast<const float4*>(gq + (size_t)row * EMB + c4);
            float* dst = &Qs[row * AST + c4];
            dst[0] = __uint_as_float(f2tf(qv.x * 0.125f));
            dst[1] = __uint_as_float(f2tf(qv.y * 0.125f));
            dst[2] = __uint_as_float(f2tf(qv.z * 0.125f));
            dst[3] = __uint_as_float(f2tf(qv.w * 0.125f));
        }
    }
    __syncthreads();

    // Preload Q fragments (reused every kv tile)
    uint32_t qf[8][4];
#pragma unroll
    for (int ks = 0; ks < 8; ks++) {
        const int kk = ks * 8;
        qf[ks][0] = __float_as_uint(Qs[(m0 + g) * AST + kk + t]);
        qf[ks][1] = __float_as_uint(Qs[(m0 + g + 8) * AST + kk + t]);
        qf[ks][2] = __float_as_uint(Qs[(m0 + g) * AST + kk + t + 4]);
        qf[ks][3] = __float_as_uint(Qs[(m0 + g + 8) * AST + kk + t + 4]);
    }

    // Row state in registers (2 rows per thread; identical across the 4 t-lanes)
    float rm0 = -1e30f, rm1 = -1e30f, rl0 = 0.f, rl1 = 0.f;
    float o[8][4];
#pragma unroll
    for (int nt = 0; nt < 8; nt++)
#pragma unroll
        for (int i = 0; i < 4; i++) o[nt][i] = 0.f;

    const int ntiles = 2 * iq + 2;   // kv tiles of 64 covering rows [0, 128(iq+1))
    for (int j = 0; j < ntiles; j++) {
        // prefetch K/V tile to regs
        float4 kv4[4], vv4[4];
        {
            const float* gk = K + base + (size_t)j * 64 * EMB;
            const float* gv = V + base + (size_t)j * 64 * EMB;
#pragma unroll
            for (int it = 0; it < 4; it++) {
                kv4[it] = *reinterpret_cast<const float4*>(gk + (size_t)krow[it] * EMB + kc4[it]);
                vv4[it] = *reinterpret_cast<const float4*>(gv + (size_t)krow[it] * EMB + kc4[it]);
            }
        }
        __syncthreads();   // previous tile fully consumed
#pragma unroll
        for (int it = 0; it < 4; it++) {
            float* dk = &Ks[krow[it] * AST + kc4[it]];
            dk[0] = __uint_as_float(f2tf(kv4[it].x));
            dk[1] = __uint_as_float(f2tf(kv4[it].y));
            dk[2] = __uint_as_float(f2tf(kv4[it].z));
            dk[3] = __uint_as_float(f2tf(kv4[it].w));
            float* dv = &Vs[krow[it] * VST + kc4[it]];
            dv[0] = __uint_as_float(f2tf(vv4[it].x));
            dv[1] = __uint_as_float(f2tf(vv4[it].y));
            dv[2] = __uint_as_float(f2tf(vv4[it].z));
            dv[3] = __uint_as_float(f2tf(vv4[it].w));
        }
        __syncthreads();

        // S = Q @ K^T  (warp's 16 rows x all 64 cols)
        float s[8][4];
#pragma unroll
        for (int nt = 0; nt < 8; nt++)
#pragma unroll
            for (int i = 0; i < 4; i++) s[nt][i] = 0.f;
#pragma unroll
        for (int ks = 0; ks < 8; ks++) {
            const int kk = ks * 8;
            uint32_t bf[8][2];
#pragma unroll
            for (int nt = 0; nt < 8; nt++) {
                const int n = nt * 8;
                bf[nt][0] = __float_as_uint(Ks[(n + g) * AST + kk + t]);
                bf[nt][1] = __float_as_uint(Ks[(n + g) * AST + kk + t + 4]);
            }
#pragma unroll
            for (int nt = 0; nt < 8; nt++) mma_tf32(s[nt], qf[ks], bf[nt]);
        }

        // Causal mask (only tiles overlapping the diagonal need it)
        if (j >= 2 * iq) {
            const int grow0 = iq * 128 + m0 + g;
            const int grow1 = grow0 + 8;
            const int cb    = j * 64;
#pragma unroll
            for (int nt = 0; nt < 8; nt++) {
                const int gc = cb + nt * 8 + 2 * t;
                if (gc     > grow0) s[nt][0] = -1e30f;
                if (gc + 1 > grow0) s[nt][1] = -1e30f;
                if (gc     > grow1) s[nt][2] = -1e30f;
                if (gc + 1 > grow1) s[nt][3] = -1e30f;
            }
        }

        // Warp-local row max
        float mx0 = -1e30f, mx1 = -1e30f;
#pragma unroll
        for (int nt = 0; nt < 8; nt++) {
            mx0 = fmaxf(mx0, fmaxf(s[nt][0], s[nt][1]));
            mx1 = fmaxf(mx1, fmaxf(s[nt][2], s[nt][3]));
        }
        mx0 = fmaxf(mx0, __shfl_xor_sync(0xffffffffu, mx0, 1));
        mx0 = fmaxf(mx0, __shfl_xor_sync(0xffffffffu, mx0, 2));
        mx1 = fmaxf(mx1, __shfl_xor_sync(0xffffffffu, mx1, 1));
        mx1 = fmaxf(mx1, __shfl_xor_sync(0xffffffffu, mx1, 2));

        const float mnew0 = fmaxf(rm0, mx0);
        const float mnew1 = fmaxf(rm1, mx1);
        const float al0 = __expf(rm0 - mnew0);
        const float al1 = __expf(rm1 - mnew1);

        float ps0 = 0.f, ps1 = 0.f;
#pragma unroll
        for (int nt = 0; nt < 8; nt++) {
            const int cc = nt * 8 + 2 * t;
            float p00 = __expf(s[nt][0] - mnew0);
            float p01 = __expf(s[nt][1] - mnew0);
            float p10 = __expf(s[nt][2] - mnew1);
            float p11 = __expf(s[nt][3] - mnew1);
            ps0 += p00 + p01;
            ps1 += p10 + p11;
            *reinterpret_cast<float2*>(&Ps[(m0 + g) * AST + cc]) =
                make_float2(__uint_as_float(f2tf(p00)), __uint_as_float(f2tf(p01)));
            *reinterpret_cast<float2*>(&Ps[(m0 + g + 8) * AST + cc]) =
                make_float2(__uint_as_float(f2tf(p10)), __uint_as_float(f2tf(p11)));
        }
        ps0 += __shfl_xor_sync(0xffffffffu, ps0, 1);
        ps0 += __shfl_xor_sync(0xffffffffu, ps0, 2);
        ps1 += __shfl_xor_sync(0xffffffffu, ps1, 1);
        ps1 += __shfl_xor_sync(0xffffffffu, ps1, 2);
        rl0 = rl0 * al0 + ps0;  rm0 = mnew0;
        rl1 = rl1 * al1 + ps1;  rm1 = mnew1;

#pragma unroll
        for (int nt = 0; nt < 8; nt++) {
            o[nt][0] *= al0; o[nt][1] *= al0;
            o[nt][2] *= al1; o[nt][3] *= al1;
        }
        __syncwarp();   // P rows are warp-private

        // O += P @ V
#pragma unroll
        for (int ks = 0; ks < 8; ks++) {
            const int kk = ks * 8;
            uint32_t af[4];
            af[0] = __float_as_uint(Ps[(m0 + g) * AST + kk + t]);
            af[1] = __float_as_uint(Ps[(m0 + g + 8) * AST + kk + t]);
            af[2] = __float_as_uint(Ps[(m0 + g) * AST + kk + t + 4]);
            af[3] = __float_as_uint(Ps[(m0 + g + 8) * AST + kk + t + 4]);
            uint32_t bf[8][2];
#pragma unroll
            for (int nt = 0; nt < 8; nt++) {
                const int n = nt * 8;
                bf[nt][0] = __float_as_uint(Vs[(kk + t) * VST + n + g]);
                bf[nt][1] = __float_as_uint(Vs[(kk + t + 4) * VST + n + g]);
            }
#pragma unroll
            for (int nt = 0; nt < 8; nt++) mma_tf32(o[nt], af, bf[nt]);
        }
    }

    const float inv0 = 1.0f / rl0;
    const float inv1 = 1.0f / rl1;

    float* go = O + base + ((size_t)iq * 128) * EMB;
#pragma unroll
    for (int nt = 0; nt < 8; nt++) {
        const int cc = nt * 8 + 2 * t;
        *reinterpret_cast<float2*>(go + (size_t)(m0 + g) * EMB + cc) =
            make_float2(o[nt][0] * inv0, o[nt][1] * inv0);
        *reinterpret_cast<float2*>(go + (size_t)(m0 + g + 8) * EMB + cc) =
            make_float2(o[nt][2] * inv1, o[nt][3] * inv1);
    }
}

// ---------------------------------------------------------------------------
// Launch. Inputs (metadata order): key, query, value, mask, Wq, Wk, Wv, Wo
// ---------------------------------------------------------------------------
extern "C" void kernel_launch(void* const* d_in, const int* in_sizes, int n_in,
                              void* d_out, int out_size) {
    const float* key   = (const float*)d_in[0];
    const float* query = (const float*)d_in[1];
    const float* value = (const float*)d_in[2];
    // d_in[3] = causal mask, implied by attn_tc
    const float* Wq = (const float*)d_in[4];
    const float* Wk = (const float*)d_in[5];
    const float* Wv = (const float*)d_in[6];
    const float* Wo = (const float*)d_in[7];
    float* out = (float*)d_out;

    void *pQ, *pK, *pV, *pO;
    cudaGetSymbolAddress(&pQ, g_Q);
    cudaGetSymbolAddress(&pK, g_K);
    cudaGetSymbolAddress(&pV, g_V);
    cudaGetSymbolAddress(&pO, g_O);

    const int smem_gemm = 4 * 128 * GST * (int)sizeof(float);   // 73728 B
    cudaFuncSetAttribute(tfgemm_nt, cudaFuncAttributeMaxDynamicSharedMemorySize, smem_gemm);

    const int smem_attn = (2 * 128 * AST + 64 * AST + 64 * VST) * (int)sizeof(float); // 105472 B
    cudaFuncSetAttribute(attn_tc, cudaFuncAttributeMaxDynamicSharedMemorySize, smem_attn);

    dim3 gGemm(EMB / 128, M_ROWS / 128);   // (8, 64)
    dim3 bGemm(256);

    tfgemm_nt<<<gGemm, bGemm, smem_gemm>>>(query, Wq, (float*)pQ, M_ROWS, EMB, EMB);
    tfgemm_nt<<<gGemm, bGemm, smem_gemm>>>(key,   Wk, (float*)pK, M_ROWS, EMB, EMB);
    tfgemm_nt<<<gGemm, bGemm, smem_gemm>>>(value, Wv, (float*)pV, M_ROWS, EMB, EMB);

    dim3 gAttn(S_LEN / 128, NH, B_SZ);     // (16, 16, 4)
    attn_tc<<<gAttn, 256, smem_attn>>>((const float*)pQ, (const float*)pK,
                                       (const float*)pV, (float*)pO);

    tfgemm_nt<<<gGemm, bGemm, smem_gemm>>>((const float*)pO, Wo, out, M_ROWS, EMB, EMB);
}

// round 10
// speedup vs baseline: 1.0003x; 1.0003x over previous
#include <cuda_runtime.h>
#include <cuda_bf16.h>
#include <cstdint>

// Problem constants
#define B_SZ 4
#define S_LEN 2048
#define EMB 1024
#define NH 16
#define DH 64
#define M_ROWS (B_SZ * S_LEN)   // 8192

// ---------------------------------------------------------------------------
// Scratch (static device globals; no runtime allocation)
// ---------------------------------------------------------------------------
__device__ float g_Q[(size_t)M_ROWS * EMB];
__device__ float g_K[(size_t)M_ROWS * EMB];
__device__ float g_V[(size_t)M_ROWS * EMB];
__device__ float g_O[(size_t)M_ROWS * EMB];

// ---------------------------------------------------------------------------
// tf32 helpers
// ---------------------------------------------------------------------------
__device__ __forceinline__ uint32_t f2tf(float x) {
    uint32_t u;
    asm("cvt.rna.tf32.f32 %0, %1;" : "=r"(u) : "f"(x));
    return u;
}

__device__ __forceinline__ void mma_tf32(float* c, const uint32_t* a, const uint32_t* b) {
    asm volatile(
        "mma.sync.aligned.m16n8k8.row.col.f32.tf32.tf32.f32 "
        "{%0,%1,%2,%3}, {%4,%5,%6,%7}, {%8,%9}, {%0,%1,%2,%3};\n"
        : "+f"(c[0]), "+f"(c[1]), "+f"(c[2]), "+f"(c[3])
        : "r"(a[0]), "r"(a[1]), "r"(a[2]), "r"(a[3]), "r"(b[0]), "r"(b[1]));
}

// ---------------------------------------------------------------------------
// tf32 GEMM: C[M,N] = A[M,K] @ B[N,K]^T  (both K-contiguous -> row.col mma)
// 128x128 block, BK=32, 8 warps (2m x 4n), warp tile 64x32.
// Double-buffered smem, ONE __syncthreads per 32-K stage.
// ---------------------------------------------------------------------------
#define GST 36   // 36 mod 32 = 4 -> conflict-free fragment reads
#define GNS (EMB / 32)   // 32 stages

__global__ __launch_bounds__(256) void tfgemm_nt(const float* __restrict__ A,
                                                 const float* __restrict__ B,
                                                 float* __restrict__ C,
                                                 int M, int N, int K) {
    extern __shared__ float gsm[];
    // two stages: [stage][A/B][128][GST]
    float* As[2] = {gsm,                gsm + 2 * 128 * GST};
    float* Bs[2] = {gsm + 128 * GST,    gsm + 3 * 128 * GST};

    const int tid  = threadIdx.x;
    const int lane = tid & 31;
    const int wid  = tid >> 5;
    const int wm   = wid >> 2;      // 0..1 -> 64-row slice
    const int wn   = wid & 3;       // 0..3 -> 32-col slice
    const int g    = lane >> 2;
    const int t    = lane & 3;

    const int bm = blockIdx.y * 128;
    const int bn = blockIdx.x * 128;

    float c[4][4][4];
#pragma unroll
    for (int mt = 0; mt < 4; mt++)
#pragma unroll
        for (int nt = 0; nt < 4; nt++)
#pragma unroll
            for (int i = 0; i < 4; i++) c[mt][nt][i] = 0.f;

    const float* Ap = A + (size_t)bm * K;
    const float* Bp = B + (size_t)bn * K;

    // loader coords: 128 rows x 8 float4 = 1024 per tensor; 4 per thread
    int lr[4], lc[4];
#pragma unroll
    for (int i = 0; i < 4; i++) {
        int idx = tid + i * 256;
        lr[i] = idx >> 3;
        lc[i] = (idx & 7) << 2;
    }

    float4 av[4], bv[4];
#pragma unroll
    for (int i = 0; i < 4; i++) {
        av[i] = *reinterpret_cast<const float4*>(Ap + (size_t)lr[i] * K + lc[i]);
        bv[i] = *reinterpret_cast<const float4*>(Bp + (size_t)lr[i] * K + lc[i]);
    }

    for (int s = 0; s < GNS; s++) {
        const int buf = s & 1;
        float* Asb = As[buf];
        float* Bsb = Bs[buf];

        // store current stage (regs -> smem, tf32-rounded)
#pragma unroll
        for (int i = 0; i < 4; i++) {
            float* da = &Asb[lr[i] * GST + lc[i]];
            da[0] = __uint_as_float(f2tf(av[i].x));
            da[1] = __uint_as_float(f2tf(av[i].y));
            da[2] = __uint_as_float(f2tf(av[i].z));
            da[3] = __uint_as_float(f2tf(av[i].w));
            float* db = &Bsb[lr[i] * GST + lc[i]];
            db[0] = __uint_as_float(f2tf(bv[i].x));
            db[1] = __uint_as_float(f2tf(bv[i].y));
            db[2] = __uint_as_float(f2tf(bv[i].z));
            db[3] = __uint_as_float(f2tf(bv[i].w));
        }

        // prefetch next stage to regs (lands during compute below)
        if (s + 1 < GNS) {
            const int k0 = (s + 1) * 32;
#pragma unroll
            for (int i = 0; i < 4; i++) {
                av[i] = *reinterpret_cast<const float4*>(Ap + (size_t)lr[i] * K + k0 + lc[i]);
                bv[i] = *reinterpret_cast<const float4*>(Bp + (size_t)lr[i] * K + k0 + lc[i]);
            }
        }

        __syncthreads();   // the ONLY barrier per stage

        // compute: 4 k-steps x (4 mt x 4 nt) MMAs
#pragma unroll
        for (int ks = 0; ks < 4; ks++) {
            const int kk = ks * 8;
            uint32_t a[4][4];
#pragma unroll
            for (int mt = 0; mt < 4; mt++) {
                const int r = wm * 64 + mt * 16;
                a[mt][0] = __float_as_uint(Asb[(r + g) * GST + kk + t]);
                a[mt][1] = __float_as_uint(Asb[(r + g + 8) * GST + kk + t]);
                a[mt][2] = __float_as_uint(Asb[(r + g) * GST + kk + t + 4]);
                a[mt][3] = __float_as_uint(Asb[(r + g + 8) * GST + kk + t + 4]);
            }
            uint32_t b[4][2];
#pragma unroll
            for (int nt = 0; nt < 4; nt++) {
                const int n = wn * 32 + nt * 8;
                b[nt][0] = __float_as_uint(Bsb[(n + g) * GST + kk + t]);
                b[nt][1] = __float_as_uint(Bsb[(n + g) * GST + kk + t + 4]);
            }
#pragma unroll
            for (int mt = 0; mt < 4; mt++)
#pragma unroll
                for (int nt = 0; nt < 4; nt++)
                    mma_tf32(c[mt][nt], a[mt], b[nt]);
        }
    }

#pragma unroll
    for (int mt = 0; mt < 4; mt++) {
#pragma unroll
        for (int nt = 0; nt < 4; nt++) {
            const int r  = bm + wm * 64 + mt * 16 + g;
            const int cn = bn + wn * 32 + nt * 8 + 2 * t;
            *reinterpret_cast<float2*>(C + (size_t)r * N + cn) =
                make_float2(c[mt][nt][0], c[mt][nt][1]);
            *reinterpret_cast<float2*>(C + (size_t)(r + 8) * N + cn) =
                make_float2(c[mt][nt][2], c[mt][nt][3]);
        }
    }
}

// ---------------------------------------------------------------------------
// Fused causal flash attention, tf32 mma.sync.
// BQ=128 q-rows per CTA, 8 warps; warp w owns rows [16w,16w+16) x ALL 64 kv
// cols -> softmax is warp-local (no cross-warp smem/barriers). Row state in
// registers. P roundtrip through warp-private smem, __syncwarp only.
// ---------------------------------------------------------------------------
#define AST 68   // 68 mod 32 = 4
#define VST 72   // 72 mod 32 = 8

__global__ __launch_bounds__(256) void attn_tc(const float* __restrict__ Q,
                                               const float* __restrict__ K,
                                               const float* __restrict__ V,
                                               float* __restrict__ O) {
    extern __shared__ float sm[];
    float* Qs = sm;                  // [128][AST]
    float* Ks = Qs + 128 * AST;      // [64][AST]
    float* Ps = Ks + 64 * AST;       // [128][AST]
    float* Vs = Ps + 128 * AST;      // [64][VST]

    const int tid  = threadIdx.x;
    const int lane = tid & 31;
    const int wid  = tid >> 5;
    const int g    = lane >> 2;
    const int t    = lane & 3;
    const int m0   = wid * 16;       // warp's row slice

    const int iq = (gridDim.x - 1) - blockIdx.x;   // heaviest CTAs first
    const int h  = blockIdx.y;
    const int b  = blockIdx.z;
    const size_t base = ((size_t)b * S_LEN) * EMB + (size_t)h * DH;

    // kv loader coords: 64 rows x 16 float4 = 1024; 4 per thread
    int krow[4], kc4[4];
#pragma unroll
    for (int it = 0; it < 4; it++) {
        int idx = tid + it * 256;
        krow[it] = idx >> 4;
        kc4[it]  = (idx & 15) << 2;
    }

    // Load Q tile: 128 rows x 16 float4 = 2048; 8 per thread (scaled, tf32)
    {
        const float* gq = Q + base + (size_t)iq * 128 * EMB;
#pragma unroll
        for (int it = 0; it < 8; it++) {
            int idx = tid + it * 256;
            int row = idx >> 4;
            int c4  = (idx & 15) << 2;
            float4 qv = *reinterpret_cast<const float4*>(gq + (size_t)row * EMB + c4);
            float* dst = &Qs[row * AST + c4];
            dst[0] = __uint_as_float(f2tf(qv.x * 0.125f));
            dst[1] = __uint_as_float(f2tf(qv.y * 0.125f));
            dst[2] = __uint_as_float(f2tf(qv.z * 0.125f));
            dst[3] = __uint_as_float(f2tf(qv.w * 0.125f));
        }
    }
    __syncthreads();

    // Preload Q fragments (reused every kv tile)
    uint32_t qf[8][4];
#pragma unroll
    for (int ks = 0; ks < 8; ks++) {
        const int kk = ks * 8;
        qf[ks][0] = __float_as_uint(Qs[(m0 + g) * AST + kk + t]);
        qf[ks][1] = __float_as_uint(Qs[(m0 + g + 8) * AST + kk + t]);
        qf[ks][2] = __float_as_uint(Qs[(m0 + g) * AST + kk + t + 4]);
        qf[ks][3] = __float_as_uint(Qs[(m0 + g + 8) * AST + kk + t + 4]);
    }

    // Row state in registers (2 rows per thread; identical across the 4 t-lanes)
    float rm0 = -1e30f, rm1 = -1e30f, rl0 = 0.f, rl1 = 0.f;
    float o[8][4];
#pragma unroll
    for (int nt = 0; nt < 8; nt++)
#pragma unroll
        for (int i = 0; i < 4; i++) o[nt][i] = 0.f;

    const int ntiles = 2 * iq + 2;   // kv tiles of 64 covering rows [0, 128(iq+1))
    for (int j = 0; j < ntiles; j++) {
        // prefetch K/V tile to regs
        float4 kv4[4], vv4[4];
        {
            const float* gk = K + base + (size_t)j * 64 * EMB;
            const float* gv = V + base + (size_t)j * 64 * EMB;
#pragma unroll
            for (int it = 0; it < 4; it++) {
                kv4[it] = *reinterpret_cast<const float4*>(gk + (size_t)krow[it] * EMB + kc4[it]);
                vv4[it] = *reinterpret_cast<const float4*>(gv + (size_t)krow[it] * EMB + kc4[it]);
            }
        }
        __syncthreads();   // previous tile fully consumed
#pragma unroll
        for (int it = 0; it < 4; it++) {
            float* dk = &Ks[krow[it] * AST + kc4[it]];
            dk[0] = __uint_as_float(f2tf(kv4[it].x));
            dk[1] = __uint_as_float(f2tf(kv4[it].y));
            dk[2] = __uint_as_float(f2tf(kv4[it].z));
            dk[3] = __uint_as_float(f2tf(kv4[it].w));
            float* dv = &Vs[krow[it] * VST + kc4[it]];
            dv[0] = __uint_as_float(f2tf(vv4[it].x));
            dv[1] = __uint_as_float(f2tf(vv4[it].y));
            dv[2] = __uint_as_float(f2tf(vv4[it].z));
            dv[3] = __uint_as_float(f2tf(vv4[it].w));
        }
        __syncthreads();

        // S = Q @ K^T  (warp's 16 rows x all 64 cols)
        float s[8][4];
#pragma unroll
        for (int nt = 0; nt < 8; nt++)
#pragma unroll
            for (int i = 0; i < 4; i++) s[nt][i] = 0.f;
#pragma unroll
        for (int ks = 0; ks < 8; ks++) {
            const int kk = ks * 8;
            uint32_t bf[8][2];
#pragma unroll
            for (int nt = 0; nt < 8; nt++) {
                const int n = nt * 8;
                bf[nt][0] = __float_as_uint(Ks[(n + g) * AST + kk + t]);
                bf[nt][1] = __float_as_uint(Ks[(n + g) * AST + kk + t + 4]);
            }
#pragma unroll
            for (int nt = 0; nt < 8; nt++) mma_tf32(s[nt], qf[ks], bf[nt]);
        }

        // Causal mask (only tiles overlapping the diagonal need it)
        if (j >= 2 * iq) {
            const int grow0 = iq * 128 + m0 + g;
            const int grow1 = grow0 + 8;
            const int cb    = j * 64;
#pragma unroll
            for (int nt = 0; nt < 8; nt++) {
                const int gc = cb + nt * 8 + 2 * t;
                if (gc     > grow0) s[nt][0] = -1e30f;
                if (gc + 1 > grow0) s[nt][1] = -1e30f;
                if (gc     > grow1) s[nt][2] = -1e30f;
                if (gc + 1 > grow1) s[nt][3] = -1e30f;
            }
        }

        // Warp-local row max
        float mx0 = -1e30f, mx1 = -1e30f;
#pragma unroll
        for (int nt = 0; nt < 8; nt++) {
            mx0 = fmaxf(mx0, fmaxf(s[nt][0], s[nt][1]));
            mx1 = fmaxf(mx1, fmaxf(s[nt][2], s[nt][3]));
        }
        mx0 = fmaxf(mx0, __shfl_xor_sync(0xffffffffu, mx0, 1));
        mx0 = fmaxf(mx0, __shfl_xor_sync(0xffffffffu, mx0, 2));
        mx1 = fmaxf(mx1, __shfl_xor_sync(0xffffffffu, mx1, 1));
        mx1 = fmaxf(mx1, __shfl_xor_sync(0xffffffffu, mx1, 2));

        const float mnew0 = fmaxf(rm0, mx0);
        const float mnew1 = fmaxf(rm1, mx1);
        const float al0 = __expf(rm0 - mnew0);
        const float al1 = __expf(rm1 - mnew1);

        float ps0 = 0.f, ps1 = 0.f;
#pragma unroll
        for (int nt = 0; nt < 8; nt++) {
            const int cc = nt * 8 + 2 * t;
            float p00 = __expf(s[nt][0] - mnew0);
            float p01 = __expf(s[nt][1] - mnew0);
            float p10 = __expf(s[nt][2] - mnew1);
            float p11 = __expf(s[nt][3] - mnew1);
            ps0 += p00 + p01;
            ps1 += p10 + p11;
            *reinterpret_cast<float2*>(&Ps[(m0 + g) * AST + cc]) =
                make_float2(__uint_as_float(f2tf(p00)), __uint_as_float(f2tf(p01)));
            *reinterpret_cast<float2*>(&Ps[(m0 + g + 8) * AST + cc]) =
                make_float2(__uint_as_float(f2tf(p10)), __uint_as_float(f2tf(p11)));
        }
        ps0 += __shfl_xor_sync(0xffffffffu, ps0, 1);
        ps0 += __shfl_xor_sync(0xffffffffu, ps0, 2);
        ps1 += __shfl_xor_sync(0xffffffffu, ps1, 1);
        ps1 += __shfl_xor_sync(0xffffffffu, ps1, 2);
        rl0 = rl0 * al0 + ps0;  rm0 = mnew0;
        rl1 = rl1 * al1 + ps1;  rm1 = mnew1;

#pragma unroll
        for (int nt = 0; nt < 8; nt++) {
            o[nt][0] *= al0; o[nt][1] *= al0;
            o[nt][2] *= al1; o[nt][3] *= al1;
        }
        __syncwarp();   // P rows are warp-private

        // O += P @ V
#pragma unroll
        for (int ks = 0; ks < 8; ks++) {
            const int kk = ks * 8;
            uint32_t af[4];
            af[0] = __float_as_uint(Ps[(m0 + g) * AST + kk + t]);
            af[1] = __float_as_uint(Ps[(m0 + g + 8) * AST + kk + t]);
            af[2] = __float_as_uint(Ps[(m0 + g) * AST + kk + t + 4]);
            af[3] = __float_as_uint(Ps[(m0 + g + 8) * AST + kk + t + 4]);
            uint32_t bf[8][2];
#pragma unroll
            for (int nt = 0; nt < 8; nt++) {
                const int n = nt * 8;
                bf[nt][0] = __float_as_uint(Vs[(kk + t) * VST + n + g]);
                bf[nt][1] = __float_as_uint(Vs[(kk + t + 4) * VST + n + g]);
            }
#pragma unroll
            for (int nt = 0; nt < 8; nt++) mma_tf32(o[nt], af, bf[nt]);
        }
    }

    const float inv0 = 1.0f / rl0;
    const float inv1 = 1.0f / rl1;

    float* go = O + base + ((size_t)iq * 128) * EMB;
#pragma unroll
    for (int nt = 0; nt < 8; nt++) {
        const int cc = nt * 8 + 2 * t;
        *reinterpret_cast<float2*>(go + (size_t)(m0 + g) * EMB + cc) =
            make_float2(o[nt][0] * inv0, o[nt][1] * inv0);
        *reinterpret_cast<float2*>(go + (size_t)(m0 + g + 8) * EMB + cc) =
            make_float2(o[nt][2] * inv1, o[nt][3] * inv1);
    }
}

// ---------------------------------------------------------------------------
// Launch. Inputs (metadata order): key, query, value, mask, Wq, Wk, Wv, Wo
// ---------------------------------------------------------------------------
extern "C" void kernel_launch(void* const* d_in, const int* in_sizes, int n_in,
                              void* d_out, int out_size) {
    const float* key   = (const float*)d_in[0];
    const float* query = (const float*)d_in[1];
    const float* value = (const float*)d_in[2];
    // d_in[3] = causal mask, implied by attn_tc
    const float* Wq = (const float*)d_in[4];
    const float* Wk = (const float*)d_in[5];
    const float* Wv = (const float*)d_in[6];
    const float* Wo = (const float*)d_in[7];
    float* out = (float*)d_out;

    void *pQ, *pK, *pV, *pO;
    cudaGetSymbolAddress(&pQ, g_Q);
    cudaGetSymbolAddress(&pK, g_K);
    cudaGetSymbolAddress(&pV, g_V);
    cudaGetSymbolAddress(&pO, g_O);

    const int smem_gemm = 4 * 128 * GST * (int)sizeof(float);   // 73728 B
    cudaFuncSetAttribute(tfgemm_nt, cudaFuncAttributeMaxDynamicSharedMemorySize, smem_gemm);

    const int smem_attn = (2 * 128 * AST + 64 * AST + 64 * VST) * (int)sizeof(float); // 105472 B
    cudaFuncSetAttribute(attn_tc, cudaFuncAttributeMaxDynamicSharedMemorySize, smem_attn);

    dim3 gGemm(EMB / 128, M_ROWS / 128);   // (8, 64)
    dim3 bGemm(256);

    tfgemm_nt<<<gGemm, bGemm, smem_gemm>>>(query, Wq, (float*)pQ, M_ROWS, EMB, EMB);
    tfgemm_nt<<<gGemm, bGemm, smem_gemm>>>(key,   Wk, (float*)pK, M_ROWS, EMB, EMB);
    tfgemm_nt<<<gGemm, bGemm, smem_gemm>>>(value, Wv, (float*)pV, M_ROWS, EMB, EMB);

    dim3 gAttn(S_LEN / 128, NH, B_SZ);     // (16, 16, 4)
    attn_tc<<<gAttn, 256, smem_attn>>>((const float*)pQ, (const float*)pK,
                                       (const float*)pV, (float*)pO);

    tfgemm_nt<<<gGemm, bGemm, smem_gemm>>>((const float*)pO, Wo, out, M_ROWS, EMB, EMB);
}